// round 6
// baseline (speedup 1.0000x reference)
#include <cuda_runtime.h>
#include <cuda_bf16.h>
#include <cstdint>

#define TT 512
#define BB 32
#define II 1024
#define HH 1024
#define G4 4096   // 4*H
#define NB 128    // persistent CTAs
#define NTH 256   // threads per CTA (recurrence)

#define KCH 48          // K' chunks of 64 (3*1024/64)
#define MT  128         // M tiles (16384/128)
#define NTB 32          // N tiles (4096/128)
#define GT_A 16384
#define GT_B 16384
#define GSTAGE_B (GT_A + GT_B)
#define GSTG 3

// recurrence smem offsets (bytes)
#define RS_H 0
#define RS_L 65536
#define YSM  131072                 // [2 buf][ hi 16K | lo 16K ]
#define REDO 196608                 // red [8][4][32] floats = 4KB
#define GSMO 200704                 // gsm [32][33] floats = 4224B
#define SMEM_REC (GSMO + 32 * 33 * 4)

// ------------------------- device scratch -------------------------
__device__ float g_gates[(size_t)TT * BB * G4];                 // 256 MB
__device__ unsigned char g_At[(size_t)KCH * MT * GT_A];
__device__ unsigned char g_Bt[(size_t)KCH * NTB * GT_B];
__device__ __nv_bfloat16 g_yh[2][BB * HH];   // y hi, [buf][b][k]
__device__ __nv_bfloat16 g_yl[2][BB * HH];   // y lo
__device__ unsigned g_cnt4[4];               // per-group step counters

// ------------------------- helpers -------------------------
__device__ __forceinline__ uint32_t smem_u32(const void* p) {
    uint32_t a;
    asm("{ .reg .u64 t; cvta.to.shared.u64 t, %1; cvt.u32.u64 %0, t; }" : "=r"(a) : "l"(p));
    return a;
}
__device__ __forceinline__ void ldsm4(uint32_t (&r)[4], uint32_t addr) {
    asm volatile("ldmatrix.sync.aligned.m8n8.x4.shared.b16 {%0,%1,%2,%3}, [%4];"
        : "=r"(r[0]), "=r"(r[1]), "=r"(r[2]), "=r"(r[3]) : "r"(addr));
}
__device__ __forceinline__ void mma16816(float (&d)[4], const uint32_t (&a)[4],
                                         uint32_t b0, uint32_t b1) {
    asm volatile("mma.sync.aligned.m16n8k16.row.col.f32.bf16.bf16.f32 "
        "{%0,%1,%2,%3}, {%4,%5,%6,%7}, {%8,%9}, {%0,%1,%2,%3};"
        : "+f"(d[0]), "+f"(d[1]), "+f"(d[2]), "+f"(d[3])
        : "r"(a[0]), "r"(a[1]), "r"(a[2]), "r"(a[3]), "r"(b0), "r"(b1));
}
__device__ __forceinline__ void cp16(uint32_t sdst, const void* gsrc) {
    asm volatile("cp.async.cg.shared.global [%0], [%1], 16;" :: "r"(sdst), "l"(gsrc) : "memory");
}
__device__ __forceinline__ void cp_commit() {
    asm volatile("cp.async.commit_group;" ::: "memory");
}
template<int N> __device__ __forceinline__ void cp_wait() {
    asm volatile("cp.async.wait_group %0;" :: "n"(N) : "memory");
}
__device__ __forceinline__ uint32_t pack_bf2(float a, float b) {
    __nv_bfloat162 h = __floats2bfloat162_rn(a, b);
    return *(uint32_t*)&h;
}
__device__ __forceinline__ float hsig(float v) {
    return __saturatef(v * 0.16666666666666666f + 0.5f);
}
__device__ __forceinline__ float htanh(float v) {
    return fminf(fmaxf(v, -1.f), 1.f);
}
__device__ __forceinline__ void poll_ge(const unsigned* p, unsigned tgt) {
    unsigned v;
    do {
        asm volatile("ld.acquire.gpu.global.u32 %0, [%1];" : "=r"(v) : "l"(p) : "memory");
    } while (v < tgt);
}

// ------------------------------------------------------------------
// Conversion kernels (unchanged)
// ------------------------------------------------------------------
__global__ __launch_bounds__(256) void convA(const float* __restrict__ x)
{
    int t = blockIdx.x * 256 + threadIdx.x;
    int cg = t & 7;
    int kc = (t >> 3) & 15;
    int m  = t >> 7;

    const float4* xp = (const float4*)(x + (size_t)m * II + kc * 64 + cg * 8);
    float4 v0 = xp[0], v1 = xp[1];
    float f[8] = {v0.x, v0.y, v0.z, v0.w, v1.x, v1.y, v1.z, v1.w};
    float hif[8], lof[8];
#pragma unroll
    for (int i = 0; i < 8; i++) {
        __nv_bfloat16 h = __float2bfloat16_rn(f[i]);
        hif[i] = __bfloat162float(h);
        lof[i] = f[i] - hif[i];
    }
    uint4 hi4 = {pack_bf2(hif[0], hif[1]), pack_bf2(hif[2], hif[3]),
                 pack_bf2(hif[4], hif[5]), pack_bf2(hif[6], hif[7])};
    uint4 lo4 = {pack_bf2(lof[0], lof[1]), pack_bf2(lof[2], lof[3]),
                 pack_bf2(lof[4], lof[5]), pack_bf2(lof[6], lof[7])};

    int mt = m >> 7, r = m & 127;
    uint32_t off = (uint32_t)r * 128 + cg * 16;
    uint32_t sw  = off ^ ((off >> 3) & 0x70);

    *(uint4*)(g_At + ((size_t)(kc +  0) * MT + mt) * GT_A + sw) = hi4;
    *(uint4*)(g_At + ((size_t)(kc + 16) * MT + mt) * GT_A + sw) = hi4;
    *(uint4*)(g_At + ((size_t)(kc + 32) * MT + mt) * GT_A + sw) = lo4;
}

__global__ __launch_bounds__(256) void convB(const float* __restrict__ W)
{
    int t = blockIdx.x * 256 + threadIdx.x;
    int cg = t & 7;
    int kc = (t >> 3) & 15;
    int n  = t >> 7;

    const float4* wp = (const float4*)(W + (size_t)n * II + kc * 64 + cg * 8);
    float4 v0 = wp[0], v1 = wp[1];
    float f[8] = {v0.x, v0.y, v0.z, v0.w, v1.x, v1.y, v1.z, v1.w};
    float hif[8], lof[8];
#pragma unroll
    for (int i = 0; i < 8; i++) {
        __nv_bfloat16 h = __float2bfloat16_rn(f[i]);
        hif[i] = __bfloat162float(h);
        lof[i] = f[i] - hif[i];
    }
    uint4 hi4 = {pack_bf2(hif[0], hif[1]), pack_bf2(hif[2], hif[3]),
                 pack_bf2(hif[4], hif[5]), pack_bf2(hif[6], hif[7])};
    uint4 lo4 = {pack_bf2(lof[0], lof[1]), pack_bf2(lof[2], lof[3]),
                 pack_bf2(lof[4], lof[5]), pack_bf2(lof[6], lof[7])};

    int nt = n >> 7, r = n & 127;
    uint32_t off = (uint32_t)r * 128 + cg * 16;
    uint32_t sw  = off ^ ((off >> 3) & 0x70);

    *(uint4*)(g_Bt + ((size_t)(kc +  0) * NTB + nt) * GT_B + sw) = hi4;
    *(uint4*)(g_Bt + ((size_t)(kc + 16) * NTB + nt) * GT_B + sw) = lo4;
    *(uint4*)(g_Bt + ((size_t)(kc + 32) * NTB + nt) * GT_B + sw) = hi4;
}

// ------------------------------------------------------------------
// HMMA pre-GEMM (2 CTA/SM hint)
// ------------------------------------------------------------------
__device__ __forceinline__ void load_stage(uint32_t sbase, int s, int c, int mt, int nt, int tid)
{
    uint32_t smA = sbase + s * GSTAGE_B;
    uint32_t smB = smA + GT_A;
    const unsigned char* gA = g_At + ((size_t)c * MT + mt) * GT_A;
    const unsigned char* gB = g_Bt + ((size_t)c * NTB + nt) * GT_B;
#pragma unroll
    for (int i = 0; i < 4; i++) {
        uint32_t off = (uint32_t)(tid + i * 256) * 16;
        cp16(smA + off, gA + off);
    }
#pragma unroll
    for (int i = 0; i < 4; i++) {
        uint32_t off = (uint32_t)(tid + i * 256) * 16;
        cp16(smB + off, gB + off);
    }
}

__global__ __launch_bounds__(256, 2) void gemm_mma(const float* __restrict__ bW,
                                                   const float* __restrict__ bR)
{
    extern __shared__ __align__(128) unsigned char smg[];
    const uint32_t sbase = smem_u32(smg);

    const int tid  = threadIdx.x;
    const int lane = tid & 31;
    const int warp = tid >> 5;
    const int wm   = warp & 3;
    const int wn   = warp >> 2;
    const int mt   = blockIdx.x;
    const int nt   = blockIdx.y;

    float acc[2][8][4];
#pragma unroll
    for (int i = 0; i < 2; i++)
#pragma unroll
        for (int j = 0; j < 8; j++)
#pragma unroll
            for (int q = 0; q < 4; q++) acc[i][j][q] = 0.f;

    load_stage(sbase, 0, 0, mt, nt, tid); cp_commit();
    load_stage(sbase, 1, 1, mt, nt, tid); cp_commit();

    const int rl = lane & 15;
    const int chalf = lane >> 4;

#pragma unroll 1
    for (int c = 0; c < KCH; c++) {
        if (c + 2 < KCH) load_stage(sbase, (c + 2) % GSTG, c + 2, mt, nt, tid);
        cp_commit();
        cp_wait<2>();
        __syncthreads();

        const uint32_t smA = sbase + (c % GSTG) * GSTAGE_B;
        const uint32_t smB = smA + GT_A;

#pragma unroll
        for (int ks = 0; ks < 4; ks++) {
            const int kb = ks * 32 + chalf * 16;
            uint32_t a[2][4];
#pragma unroll
            for (int i = 0; i < 2; i++) {
                uint32_t off = (uint32_t)(wm * 32 + i * 16 + rl) * 128 + kb;
                ldsm4(a[i], smA + (off ^ ((off >> 3) & 0x70)));
            }
            uint32_t b[4][4];
#pragma unroll
            for (int j = 0; j < 4; j++) {
                uint32_t off = (uint32_t)(wn * 64 + j * 16 + rl) * 128 + kb;
                ldsm4(b[j], smB + (off ^ ((off >> 3) & 0x70)));
            }
#pragma unroll
            for (int i = 0; i < 2; i++)
#pragma unroll
                for (int j = 0; j < 4; j++) {
                    mma16816(acc[i][2 * j + 0], a[i], b[j][0], b[j][2]);
                    mma16816(acc[i][2 * j + 1], a[i], b[j][1], b[j][3]);
                }
        }
        __syncthreads();
    }

    const int m0  = mt * 128 + wm * 32 + (lane >> 2);
    const int n0g = nt * 128 + wn * 64;
#pragma unroll
    for (int i = 0; i < 2; i++) {
#pragma unroll
        for (int j = 0; j < 8; j++) {
            int n = n0g + j * 8 + (lane & 3) * 2;
            float bx = bW[n] + bR[n];
            float by = bW[n + 1] + bR[n + 1];
            int r0 = m0 + i * 16;
            float2 o0 = {acc[i][j][0] + bx, acc[i][j][1] + by};
            float2 o1 = {acc[i][j][2] + bx, acc[i][j][3] + by};
            *(float2*)&g_gates[(size_t)r0 * G4 + n] = o0;
            *(float2*)&g_gates[(size_t)(r0 + 8) * G4 + n] = o1;
        }
    }
}

// ------------------------------------------------------------------
// Init: reset counters; y0 -> bf16 hi/lo buffers
// ------------------------------------------------------------------
__global__ __launch_bounds__(256) void init_kernel(const float* __restrict__ y0)
{
    int i = blockIdx.x * 256 + threadIdx.x;   // 0..32767
    if (i < 4) g_cnt4[i] = 0;
    float v = y0[i];
    __nv_bfloat16 h = __float2bfloat16_rn(v);
    g_yh[0][i] = h;
    g_yl[0][i] = __float2bfloat16_rn(v - __bfloat162float(h));
}

// ------------------------------------------------------------------
// Persistent tensor-core recurrence with per-group sub-barriers.
// ------------------------------------------------------------------
extern __shared__ __align__(128) unsigned char smrec[];

__device__ __forceinline__ void issue_y_chunk(uint32_t sbase, int buf, int c,
                                              const __nv_bfloat16* __restrict__ yhg,
                                              const __nv_bfloat16* __restrict__ ylg,
                                              int tid)
{
#pragma unroll
    for (int i = 0; i < 8; i++) {
        int gran = tid + i * 256;              // 0..2047
        int half = gran >> 10;
        int bb   = (gran >> 5) & 31;
        int gi   = gran & 31;
        const __nv_bfloat16* src = (half ? ylg : yhg) + bb * 1024 + c * 256 + gi * 8;
        uint32_t dst = sbase + YSM + buf * 32768 + half * 16384 + bb * 512
                     + (((uint32_t)gi * 16) ^ (((uint32_t)bb & 7) << 4));
        cp16(dst, src);
    }
    cp_commit();
}

__global__ __launch_bounds__(NTH, 1) void lstm_persist(const float* __restrict__ R,
                                                       const float* __restrict__ c0,
                                                       float* __restrict__ yout,
                                                       float* __restrict__ cout)
{
    const int tid = threadIdx.x;
    const int blk = blockIdx.x;
    const uint32_t sbase = smem_u32(smrec);

    // ---- load + split + swizzle R slice into SMEM (once) ----
    for (int i = tid; i < 4096; i += NTH) {
        int rr  = i >> 7;
        int g16 = i & 127;
        int G   = (rr >> 3) * HH + blk * 8 + (rr & 7);
        const float4* p = (const float4*)(R + (size_t)G * HH + g16 * 8);
        float4 v0 = p[0], v1 = p[1];
        float f[8] = {v0.x, v0.y, v0.z, v0.w, v1.x, v1.y, v1.z, v1.w};
        float hif[8], lof[8];
#pragma unroll
        for (int j = 0; j < 8; j++) {
            __nv_bfloat16 h = __float2bfloat16_rn(f[j]);
            hif[j] = __bfloat162float(h);
            lof[j] = f[j] - hif[j];
        }
        uint4 hi4 = {pack_bf2(hif[0], hif[1]), pack_bf2(hif[2], hif[3]),
                     pack_bf2(hif[4], hif[5]), pack_bf2(hif[6], hif[7])};
        uint4 lo4 = {pack_bf2(lof[0], lof[1]), pack_bf2(lof[2], lof[3]),
                     pack_bf2(lof[4], lof[5]), pack_bf2(lof[6], lof[7])};
        uint32_t off = (uint32_t)rr * 2048 + (((uint32_t)g16 * 16) ^ (((uint32_t)rr & 7) << 4));
        *(uint4*)(smrec + RS_H + off) = hi4;
        *(uint4*)(smrec + RS_L + off) = lo4;
    }
    __syncthreads();

    const int lane  = tid & 31;
    const int warp  = tid >> 5;
    const int wm    = warp & 1;
    const int wn    = (warp >> 1) & 1;
    const int wk    = warp >> 2;
    const int chalf = lane >> 4;

    const int b  = tid >> 3;
    const int hl = tid & 7;
    const int h  = blk * 8 + hl;
    const int cstart = blk >> 5;

    float c_val = c0[(size_t)b * HH + h];

    float* red = (float*)(smrec + REDO);
    float* gsm = (float*)(smrec + GSMO);

    const uint32_t arow = (uint32_t)(wm * 16 + (lane & 15));
    const uint32_t nrow = (uint32_t)(wn * 16 + (lane & 15));
    const uint32_t aswz = (arow & 7) << 4;
    const uint32_t nswz = (nrow & 7) << 4;
    const uint32_t rbase_h = sbase + RS_H + nrow * 2048;
    const uint32_t rbase_l = sbase + RS_L + nrow * 2048;

    for (int t = 0; t < TT; t++) {
        const int rbuf = t & 1;
        const __nv_bfloat16* yhg = g_yh[rbuf];
        const __nv_bfloat16* ylg = g_yl[rbuf];

        const float* gp = g_gates + (size_t)t * BB * G4 + (size_t)b * G4 + h;
        float gp0 = gp[0 * HH], gp1 = gp[1 * HH], gp2 = gp[2 * HH], gp3 = gp[3 * HH];

        float acc0[4] = {0.f, 0.f, 0.f, 0.f};
        float acc1[4] = {0.f, 0.f, 0.f, 0.f};

        const unsigned tgt = 32u * (unsigned)t;

        poll_ge(&g_cnt4[cstart], tgt);
        issue_y_chunk(sbase, 0, cstart, yhg, ylg, tid);

#pragma unroll
        for (int i = 0; i < 4; i++) {
            const int c = (cstart + i) & 3;
            if (i < 3) {
                const int cn = (cstart + i + 1) & 3;
                poll_ge(&g_cnt4[cn], tgt);
                issue_y_chunk(sbase, (i + 1) & 1, cn, yhg, ylg, tid);
                cp_wait<1>();
            } else {
                cp_wait<0>();
            }
            __syncthreads();

            const uint32_t ybh = sbase + YSM + (i & 1) * 32768 + arow * 512;
            const uint32_t ybl = ybh + 16384;
            const uint32_t kcb = (uint32_t)c * 512;

#pragma unroll
            for (int s2 = 0; s2 < 8; s2++) {
                const int s = s2 * 2 + wk;
                const uint32_t aoff = (uint32_t)(s * 32 + chalf * 16);
                const uint32_t koff = kcb + aoff;
                uint32_t ah[4], al[4], bh[4], bl[4];
                ldsm4(ah, ybh + (aoff ^ aswz));
                ldsm4(bh, rbase_h + (koff ^ nswz));
                ldsm4(bl, rbase_l + (koff ^ nswz));
                ldsm4(al, ybl + (aoff ^ aswz));
                mma16816(acc0, ah, bh[0], bh[2]);
                mma16816(acc1, ah, bh[1], bh[3]);
                mma16816(acc0, ah, bl[0], bl[2]);
                mma16816(acc1, ah, bl[1], bl[3]);
                mma16816(acc0, al, bh[0], bh[2]);
                mma16816(acc1, al, bh[1], bh[3]);
            }
            __syncthreads();
        }

        // ---- k-split reduce ----
        if (wk == 1) {
            const int w4 = warp & 3;
#pragma unroll
            for (int j = 0; j < 4; j++) {
                red[((j)     * 4 + w4) * 32 + lane] = acc0[j];
                red[((j + 4) * 4 + w4) * 32 + lane] = acc1[j];
            }
        }
        __syncthreads();
        if (wk == 0) {
            const int w4 = warp & 3;
#pragma unroll
            for (int j = 0; j < 4; j++) {
                acc0[j] += red[((j)     * 4 + w4) * 32 + lane];
                acc1[j] += red[((j + 4) * 4 + w4) * 32 + lane];
            }
            const int mrow = wm * 16 + (lane >> 2);
            const int nb0  = wn * 16 + (lane & 3) * 2;
            gsm[(nb0 + 0) * 33 + mrow] = acc0[0];
            gsm[(nb0 + 1) * 33 + mrow] = acc0[1];
            gsm[(nb0 + 0) * 33 + mrow + 8] = acc0[2];
            gsm[(nb0 + 1) * 33 + mrow + 8] = acc0[3];
            gsm[(nb0 + 8) * 33 + mrow] = acc1[0];
            gsm[(nb0 + 9) * 33 + mrow] = acc1[1];
            gsm[(nb0 + 8) * 33 + mrow + 8] = acc1[2];
            gsm[(nb0 + 9) * 33 + mrow + 8] = acc1[3];
        }
        __syncthreads();

        // ---- gate epilogue ----
        {
            float si  = gp0 + gsm[(0 * 8 + hl) * 33 + b];
            float sf  = gp1 + gsm[(1 * 8 + hl) * 33 + b];
            float sz  = gp2 + gsm[(2 * 8 + hl) * 33 + b];
            float so4 = gp3 + gsm[(3 * 8 + hl) * 33 + b];
            float i_ = hsig(si);
            float f_ = hsig(sf);
            float z_ = htanh(sz);
            float o_ = hsig(so4);
            c_val = f_ * c_val + i_ * z_;
            float y_ = o_ * htanh(c_val);

            size_t oidx = (size_t)t * BB * HH + (size_t)b * HH + h;
            yout[oidx] = y_;
            cout[oidx] = c_val;

            __nv_bfloat16 yh = __float2bfloat16_rn(y_);
            g_yh[(t + 1) & 1][b * HH + h] = yh;
            g_yl[(t + 1) & 1][b * HH + h] = __float2bfloat16_rn(y_ - __bfloat162float(yh));
        }

        __syncthreads();
        if (tid == 0 && t < TT - 1) {
            asm volatile("red.release.gpu.global.add.u32 [%0], %1;"
                         :: "l"(&g_cnt4[blk >> 5]), "r"(1u) : "memory");
        }
    }
}

// ------------------------------------------------------------------
extern "C" void kernel_launch(void* const* d_in, const int* in_sizes, int n_in,
                              void* d_out, int out_size)
{
    const float* y0 = (const float*)d_in[0];
    const float* c0 = (const float*)d_in[1];
    const float* x  = (const float*)d_in[2];
    const float* W  = (const float*)d_in[3];
    const float* R  = (const float*)d_in[4];
    const float* bW = (const float*)d_in[5];
    const float* bR = (const float*)d_in[6];

    float* yout = (float*)d_out;
    float* cout = yout + (size_t)TT * BB * HH;

    const int smem_gemm = GSTG * GSTAGE_B;     // 98304
    cudaFuncSetAttribute(gemm_mma, cudaFuncAttributeMaxDynamicSharedMemorySize, smem_gemm);
    cudaFuncSetAttribute(lstm_persist, cudaFuncAttributeMaxDynamicSharedMemorySize, SMEM_REC);

    convA<<<8192, 256>>>(x);
    convB<<<2048, 256>>>(W);
    init_kernel<<<128, 256>>>(y0);
    gemm_mma<<<dim3(MT, NTB), 256, smem_gemm>>>(bW, bR);
    lstm_persist<<<NB, NTH, SMEM_REC>>>(R, c0, yout, cout);
}